// round 2
// baseline (speedup 1.0000x reference)
#include <cuda_runtime.h>
#include <math.h>

#define B_ 8
#define N_ 65536
#define D_ 16
#define K_ 8
#define M_ 8
#define NBLK 64
#define RED_THREADS 256
#define C_THREADS 256
#define CPT 4

// Scratch (no cudaMalloc allowed)
__device__ float g_partials[B_ * NBLK * D_]; // [b][blk][16]
__device__ float g_op[B_ * D_ * D_];         // [b][j][l]

// ---------------------------------------------------------------------------
// Kernel A: partial sums of cpu_state over N, per batch.
// ---------------------------------------------------------------------------
__global__ void gss_reduce_kernel(const float* __restrict__ cpu_state) {
    int b   = blockIdx.y;
    int blk = blockIdx.x;
    const float4* src = (const float4*)(cpu_state + (size_t)b * N_ * D_);
    const int T = RED_THREADS * NBLK;          // threads per batch (16384, %4==0)
    int t = blk * RED_THREADS + threadIdx.x;
    const int total4 = N_ * D_ / 4;            // 262144
    float4 acc = make_float4(0.f, 0.f, 0.f, 0.f);
    for (int i = t; i < total4; i += T) {
        float4 v = src[i];
        acc.x += v.x; acc.y += v.y; acc.z += v.z; acc.w += v.w;
    }
    __shared__ float4 sm[RED_THREADS];
    sm[threadIdx.x] = acc;
    __syncthreads();
    // tree reduce keeping (tid % 4) groups separate (offsets are multiples of 4)
    for (int off = RED_THREADS / 2; off >= 4; off >>= 1) {
        if (threadIdx.x < off) {
            float4 o = sm[threadIdx.x + off];
            float4 m = sm[threadIdx.x];
            m.x += o.x; m.y += o.y; m.z += o.z; m.w += o.w;
            sm[threadIdx.x] = m;
        }
        __syncthreads();
    }
    if (threadIdx.x < 4) {
        // sm[q] holds sum of quarter q (dims 4q..4q+3)
        int q = threadIdx.x;
        float4 v = sm[q];
        float* dst = g_partials + (b * NBLK + blk) * 16 + q * 4;
        dst[0] = v.x; dst[1] = v.y; dst[2] = v.z; dst[3] = v.w;
    }
}

// ---------------------------------------------------------------------------
// Threefry-2x32 (20 rounds, standard constants — matches JAX)
// ---------------------------------------------------------------------------
__device__ __forceinline__ unsigned tf_rotl(unsigned v, int d) {
    return (v << d) | (v >> (32 - d));
}

__device__ void threefry2x32(unsigned k0, unsigned k1,
                             unsigned c0, unsigned c1,
                             unsigned& o0, unsigned& o1) {
    unsigned ks0 = k0, ks1 = k1, ks2 = k0 ^ k1 ^ 0x1BD11BDAu;
    unsigned x0 = c0 + ks0;
    unsigned x1 = c1 + ks1;
    const int r0[4] = {13, 15, 26, 6};
    const int r1[4] = {17, 29, 16, 24};
#define TF_BLOCK(R)                                            \
    {                                                          \
        _Pragma("unroll")                                      \
        for (int q = 0; q < 4; q++) {                          \
            x0 += x1;                                          \
            x1 = tf_rotl(x1, (R)[q]);                          \
            x1 ^= x0;                                          \
        }                                                      \
    }
    TF_BLOCK(r0); x0 += ks1; x1 += ks2 + 1u;
    TF_BLOCK(r1); x0 += ks2; x1 += ks0 + 2u;
    TF_BLOCK(r0); x0 += ks0; x1 += ks1 + 3u;
    TF_BLOCK(r1); x0 += ks1; x1 += ks2 + 4u;
    TF_BLOCK(r0); x0 += ks2; x1 += ks0 + 5u;
#undef TF_BLOCK
    o0 = x0; o1 = x1;
}

// Cayley sign for Cl(3,0,1): replicate the reference's loop exactly.
__device__ float cayley_sign(int a, int b) {
    float s = 1.f;
#pragma unroll
    for (int i = 0; i < 4; i++) {
        if ((b >> i) & 1) {
            if (__popc(a >> (i + 1)) & 1) s = -s;
            if ((a >> i) & 1) s *= (i == 0 ? 0.f : 1.f);  // metric = [0,1,1,1]
        }
    }
    return s;
}

// ---------------------------------------------------------------------------
// Kernel B: tiny per-batch pipeline. One warp per batch.
// ---------------------------------------------------------------------------
__global__ void gss_small_kernel(const float* __restrict__ ctrl,
                                 const float* __restrict__ rule_mem,
                                 const float* __restrict__ templates,
                                 const float* __restrict__ W1,
                                 const float* __restrict__ b1,
                                 const float* __restrict__ W2,
                                 const float* __restrict__ b2,
                                 const float* __restrict__ Wr,
                                 const float* __restrict__ br,
                                 const float* __restrict__ log_temp) {
    __shared__ float summ[B_][16];
    __shared__ float si[B_][9];
    __shared__ float hid[B_][64];
    __shared__ float sc[B_][8];
    __shared__ float rs[B_][16];
    __shared__ float rmod[B_][128];
    __shared__ float wts[B_][8];
    __shared__ float comb[B_][16];

    int warp = threadIdx.x >> 5;
    int lane = threadIdx.x & 31;
    int b = warp;  // 8 warps, one per batch

    // cpu_summary = mean over N
    if (lane < 16) {
        float s = 0.f;
        for (int blk = 0; blk < NBLK; blk++)
            s += g_partials[(b * NBLK + blk) * 16 + lane];
        summ[b][lane] = s * (1.0f / N_);
    }
    __syncwarp();

    // grade norms (grades 0..4 by popcount), then ctrl
    if (lane < 5) {
        float s = 0.f;
        for (int d = 0; d < 16; d++)
            if (__popc(d) == lane) { float v = summ[b][d]; s += v * v; }
        si[b][lane] = sqrtf(s + 1e-12f);
    }
    if (lane >= 5 && lane < 9) si[b][lane] = ctrl[b * 4 + (lane - 5)];
    __syncwarp();

    // hidden = relu(si @ W1 + b1), HID=64
    for (int h = lane; h < 64; h += 32) {
        float a = b1[h];
#pragma unroll
        for (int i = 0; i < 9; i++) a += si[b][i] * W1[i * 64 + h];
        hid[b][h] = fmaxf(a, 0.f);
    }
    __syncwarp();

    // scores = hid @ W2 + b2, K=8
    if (lane < 8) {
        float a = b2[lane];
        for (int h = 0; h < 64; h++) a += hid[b][h] * W2[h * 8 + lane];
        sc[b][lane] = a;
    }

    // rule summary (mean over M=8)
    if (lane < 16) {
        float s = 0.f;
        for (int m = 0; m < M_; m++) s += rule_mem[(b * M_ + m) * 16 + lane];
        rs[b][lane] = s * (1.0f / M_);
    }
    __syncwarp();

    // rule_mod = rs @ Wr + br  [128]
    for (int j = lane; j < 128; j += 32) {
        float a = br[j];
#pragma unroll
        for (int d = 0; d < 16; d++) a += rs[b][d] * Wr[d * 128 + j];
        rmod[b][j] = a;
    }
    __syncwarp();

    // gumbel logits: (scores + g) / tau
    // JAX threefry_partitionable=True (modern default): per-element counter
    // (hi, lo) = (0, e) for flat index e; 32-bit output bits = o0 ^ o1.
    if (lane < 8) {
        int e = b * 8 + lane;  // flat index in [0,64)
        unsigned o0, o1;
        threefry2x32(0u, 42u, 0u, (unsigned)e, o0, o1);
        unsigned bits = o0 ^ o1;
        float u = __uint_as_float((bits >> 9) | 0x3f800000u) - 1.0f;
        const float minv = 1e-6f, maxv = 1.0f - 1e-6f;
        u = fmaxf(minv, u * (maxv - minv) + minv);
        float g = -logf(-logf(u));
        float tau = fminf(fmaxf(expf(log_temp[0]), 0.1f), 5.0f);
        wts[b][lane] = (sc[b][lane] + g) / tau;
    }
    __syncwarp();

    // softmax over K
    if (lane == 0) {
        float mx = -1e30f;
        for (int k = 0; k < 8; k++) mx = fmaxf(mx, wts[b][k]);
        float s = 0.f;
        for (int k = 0; k < 8; k++) { float e = expf(wts[b][k] - mx); wts[b][k] = e; s += e; }
        float inv = 1.0f / s;
        for (int k = 0; k < 8; k++) wts[b][k] *= inv;
    }
    __syncwarp();

    // combined instruction multivector: comb[i] = sum_k w_k * score_k * templ[k][i]
    if (lane < 16) {
        float s = 0.f;
        for (int k = 0; k < 8; k++) {
            float t = templates[k * 16 + lane] + rmod[b][k * 16 + lane];
            s += wts[b][k] * sc[b][k] * t;
        }
        comb[b][lane] = s;
    }
    __syncwarp();

    // Operator: Op[j][l] = comb[j^l] * sign(j^l, j)
    for (int idx = lane; idx < 256; idx += 32) {
        int j = idx >> 4, l = idx & 15;
        int i = j ^ l;
        g_op[b * 256 + idx] = comb[b][i] * cayley_sign(i, j);
    }
}

// ---------------------------------------------------------------------------
// Kernel C: apply 16x16 operator to every cell: y_l = sum_j x_j * Op[j][l]
// ---------------------------------------------------------------------------
__global__ void gss_apply_kernel(const float* __restrict__ state,
                                 float* __restrict__ out) {
    int b = blockIdx.y;
    __shared__ float opS[256];
    if (threadIdx.x < 256)
        opS[threadIdx.x] = g_op[b * 256 + threadIdx.x];
    __syncthreads();

    const size_t base4 = (size_t)b * N_ * 4;  // float4 units
    const float4* src = (const float4*)state + base4;
    float4* dst = (float4*)out + base4;

    int n0 = blockIdx.x * (C_THREADS * CPT) + threadIdx.x;
#pragma unroll
    for (int t = 0; t < CPT; t++) {
        int n = n0 + t * C_THREADS;
        float4 x0 = src[n * 4 + 0];
        float4 x1 = src[n * 4 + 1];
        float4 x2 = src[n * 4 + 2];
        float4 x3 = src[n * 4 + 3];
        float xs[16] = {x0.x, x0.y, x0.z, x0.w,
                        x1.x, x1.y, x1.z, x1.w,
                        x2.x, x2.y, x2.z, x2.w,
                        x3.x, x3.y, x3.z, x3.w};
        float4 y0 = make_float4(0.f, 0.f, 0.f, 0.f);
        float4 y1 = y0, y2 = y0, y3 = y0;
#pragma unroll
        for (int j = 0; j < 16; j++) {
            float xj = xs[j];
            const float* o = opS + j * 16;
            y0.x += xj * o[0];  y0.y += xj * o[1];  y0.z += xj * o[2];  y0.w += xj * o[3];
            y1.x += xj * o[4];  y1.y += xj * o[5];  y1.z += xj * o[6];  y1.w += xj * o[7];
            y2.x += xj * o[8];  y2.y += xj * o[9];  y2.z += xj * o[10]; y2.w += xj * o[11];
            y3.x += xj * o[12]; y3.y += xj * o[13]; y3.z += xj * o[14]; y3.w += xj * o[15];
        }
        dst[n * 4 + 0] = y0;
        dst[n * 4 + 1] = y1;
        dst[n * 4 + 2] = y2;
        dst[n * 4 + 3] = y3;
    }
}

extern "C" void kernel_launch(void* const* d_in, const int* in_sizes, int n_in,
                              void* d_out, int out_size) {
    const float* cpu_state   = (const float*)d_in[0];
    const float* ctrl_cursor = (const float*)d_in[1];
    const float* rule_memory = (const float*)d_in[2];
    const float* templates   = (const float*)d_in[3];
    const float* W1          = (const float*)d_in[4];
    const float* b1          = (const float*)d_in[5];
    const float* W2          = (const float*)d_in[6];
    const float* b2          = (const float*)d_in[7];
    const float* Wr          = (const float*)d_in[8];
    const float* br          = (const float*)d_in[9];
    const float* log_temp    = (const float*)d_in[10];
    float* out = (float*)d_out;

    dim3 gA(NBLK, B_);
    gss_reduce_kernel<<<gA, RED_THREADS>>>(cpu_state);

    gss_small_kernel<<<1, 256>>>(ctrl_cursor, rule_memory, templates,
                                 W1, b1, W2, b2, Wr, br, log_temp);

    dim3 gC(N_ / (C_THREADS * CPT), B_);
    gss_apply_kernel<<<gC, C_THREADS>>>(cpu_state, out);
}

// round 3
// speedup vs baseline: 1.0586x; 1.0586x over previous
#include <cuda_runtime.h>
#include <math.h>

#define B_ 8
#define N_ 65536
#define D_ 16
#define K_ 8
#define M_ 8
#define NBLK 128
#define RED_THREADS 256
#define C_THREADS 256

// Scratch (no cudaMalloc allowed)
__device__ float g_partials[B_ * NBLK * D_];          // [b][blk][16]
__device__ __align__(16) float g_comb[B_ * 16];       // [b][16]

// ---------------------------------------------------------------------------
// Compile-time Cayley sign for Cl(3,0,1), replicating the reference loop.
// csign(i, j) = sign of e_i * e_j contribution (0 if both contain e0).
// ---------------------------------------------------------------------------
__host__ __device__ constexpr int cpop4(unsigned v) {
    return (int)((v & 1u) + ((v >> 1) & 1u) + ((v >> 2) & 1u) + ((v >> 3) & 1u));
}
__host__ __device__ constexpr float csign(int i, int j) {
    float s = 1.0f;
    for (int b = 0; b < 4; b++) {
        if ((j >> b) & 1) {
            if (cpop4((unsigned)(i >> (b + 1))) & 1) s = -s;
            if ((i >> b) & 1) {
                if (b == 0) s = 0.0f;  // metric[0] = 0
            }
        }
    }
    return s;
}

// ---------------------------------------------------------------------------
// Kernel A: partial sums of cpu_state over N, per batch.
// grid (128, B), 256 threads; each thread does 8 fully-unrolled float4 loads.
// ---------------------------------------------------------------------------
__global__ void gss_reduce_kernel(const float* __restrict__ cpu_state) {
    int b = blockIdx.y;
    const float4* src = (const float4*)(cpu_state + (size_t)b * N_ * D_);
    const int T = NBLK * RED_THREADS;            // 32768 threads per batch (%4==0)
    int t = blockIdx.x * RED_THREADS + threadIdx.x;

    float4 v0 = src[t + 0 * T];
    float4 v1 = src[t + 1 * T];
    float4 v2 = src[t + 2 * T];
    float4 v3 = src[t + 3 * T];
    float4 v4 = src[t + 4 * T];
    float4 v5 = src[t + 5 * T];
    float4 v6 = src[t + 6 * T];
    float4 v7 = src[t + 7 * T];

    float4 acc;
    acc.x = ((v0.x + v1.x) + (v2.x + v3.x)) + ((v4.x + v5.x) + (v6.x + v7.x));
    acc.y = ((v0.y + v1.y) + (v2.y + v3.y)) + ((v4.y + v5.y) + (v6.y + v7.y));
    acc.z = ((v0.z + v1.z) + (v2.z + v3.z)) + ((v4.z + v5.z) + (v6.z + v7.z));
    acc.w = ((v0.w + v1.w) + (v2.w + v3.w)) + ((v4.w + v5.w) + (v6.w + v7.w));

    __shared__ float4 sm[RED_THREADS];
    sm[threadIdx.x] = acc;
    __syncthreads();
    // tree reduce keeping (tid % 4) groups separate (offsets are multiples of 4)
    for (int off = RED_THREADS / 2; off >= 4; off >>= 1) {
        if (threadIdx.x < off) {
            float4 o = sm[threadIdx.x + off];
            float4 m = sm[threadIdx.x];
            m.x += o.x; m.y += o.y; m.z += o.z; m.w += o.w;
            sm[threadIdx.x] = m;
        }
        __syncthreads();
    }
    if (threadIdx.x < 4) {
        int q = threadIdx.x;   // quarter q holds dims 4q..4q+3
        float4 v = sm[q];
        float* dst = g_partials + (b * NBLK + blockIdx.x) * 16 + q * 4;
        dst[0] = v.x; dst[1] = v.y; dst[2] = v.z; dst[3] = v.w;
    }
}

// ---------------------------------------------------------------------------
// Threefry-2x32 (JAX partitionable scheme: counter (0, e), bits = o0^o1)
// ---------------------------------------------------------------------------
__device__ __forceinline__ unsigned tf_rotl(unsigned v, int d) {
    return (v << d) | (v >> (32 - d));
}

__device__ void threefry2x32(unsigned k0, unsigned k1,
                             unsigned c0, unsigned c1,
                             unsigned& o0, unsigned& o1) {
    unsigned ks0 = k0, ks1 = k1, ks2 = k0 ^ k1 ^ 0x1BD11BDAu;
    unsigned x0 = c0 + ks0;
    unsigned x1 = c1 + ks1;
    const int r0[4] = {13, 15, 26, 6};
    const int r1[4] = {17, 29, 16, 24};
#define TF_BLOCK(R)                                            \
    {                                                          \
        _Pragma("unroll")                                      \
        for (int q = 0; q < 4; q++) {                          \
            x0 += x1;                                          \
            x1 = tf_rotl(x1, (R)[q]);                          \
            x1 ^= x0;                                          \
        }                                                      \
    }
    TF_BLOCK(r0); x0 += ks1; x1 += ks2 + 1u;
    TF_BLOCK(r1); x0 += ks2; x1 += ks0 + 2u;
    TF_BLOCK(r0); x0 += ks0; x1 += ks1 + 3u;
    TF_BLOCK(r1); x0 += ks1; x1 += ks2 + 4u;
    TF_BLOCK(r0); x0 += ks2; x1 += ks0 + 5u;
#undef TF_BLOCK
    o0 = x0; o1 = x1;
}

// ---------------------------------------------------------------------------
// Kernel B: tiny per-batch pipeline. One warp per batch. Publishes g_comb.
// ---------------------------------------------------------------------------
__global__ void gss_small_kernel(const float* __restrict__ ctrl,
                                 const float* __restrict__ rule_mem,
                                 const float* __restrict__ templates,
                                 const float* __restrict__ W1,
                                 const float* __restrict__ b1,
                                 const float* __restrict__ W2,
                                 const float* __restrict__ b2,
                                 const float* __restrict__ Wr,
                                 const float* __restrict__ br,
                                 const float* __restrict__ log_temp) {
    __shared__ float summ[B_][16];
    __shared__ float si[B_][9];
    __shared__ float hid[B_][64];
    __shared__ float sc[B_][8];
    __shared__ float rs[B_][16];
    __shared__ float rmod[B_][128];
    __shared__ float wts[B_][8];

    int warp = threadIdx.x >> 5;
    int lane = threadIdx.x & 31;
    int b = warp;  // 8 warps, one per batch

    // cpu_summary = mean over N
    if (lane < 16) {
        float s = 0.f;
#pragma unroll 8
        for (int blk = 0; blk < NBLK; blk++)
            s += g_partials[(b * NBLK + blk) * 16 + lane];
        summ[b][lane] = s * (1.0f / N_);
    }
    __syncwarp();

    // grade norms (grades 0..4 by popcount), then ctrl
    if (lane < 5) {
        float s = 0.f;
        for (int d = 0; d < 16; d++)
            if (__popc(d) == lane) { float v = summ[b][d]; s += v * v; }
        si[b][lane] = sqrtf(s + 1e-12f);
    }
    if (lane >= 5 && lane < 9) si[b][lane] = ctrl[b * 4 + (lane - 5)];
    __syncwarp();

    // hidden = relu(si @ W1 + b1), HID=64
    for (int h = lane; h < 64; h += 32) {
        float a = b1[h];
#pragma unroll
        for (int i = 0; i < 9; i++) a += si[b][i] * W1[i * 64 + h];
        hid[b][h] = fmaxf(a, 0.f);
    }
    __syncwarp();

    // scores = hid @ W2 + b2, K=8
    if (lane < 8) {
        float a = b2[lane];
        for (int h = 0; h < 64; h++) a += hid[b][h] * W2[h * 8 + lane];
        sc[b][lane] = a;
    }

    // rule summary (mean over M=8)
    if (lane < 16) {
        float s = 0.f;
        for (int m = 0; m < M_; m++) s += rule_mem[(b * M_ + m) * 16 + lane];
        rs[b][lane] = s * (1.0f / M_);
    }
    __syncwarp();

    // rule_mod = rs @ Wr + br  [128]
    for (int j = lane; j < 128; j += 32) {
        float a = br[j];
#pragma unroll
        for (int d = 0; d < 16; d++) a += rs[b][d] * Wr[d * 128 + j];
        rmod[b][j] = a;
    }
    __syncwarp();

    // gumbel logits: (scores + g) / tau
    if (lane < 8) {
        int e = b * 8 + lane;  // flat index in [0,64)
        unsigned o0, o1;
        threefry2x32(0u, 42u, 0u, (unsigned)e, o0, o1);
        unsigned bits = o0 ^ o1;
        float u = __uint_as_float((bits >> 9) | 0x3f800000u) - 1.0f;
        const float minv = 1e-6f, maxv = 1.0f - 1e-6f;
        u = fmaxf(minv, u * (maxv - minv) + minv);
        float g = -logf(-logf(u));
        float tau = fminf(fmaxf(expf(log_temp[0]), 0.1f), 5.0f);
        wts[b][lane] = (sc[b][lane] + g) / tau;
    }
    __syncwarp();

    // softmax over K
    if (lane == 0) {
        float mx = -1e30f;
        for (int k = 0; k < 8; k++) mx = fmaxf(mx, wts[b][k]);
        float s = 0.f;
        for (int k = 0; k < 8; k++) { float e = expf(wts[b][k] - mx); wts[b][k] = e; s += e; }
        float inv = 1.0f / s;
        for (int k = 0; k < 8; k++) wts[b][k] *= inv;
    }
    __syncwarp();

    // combined instruction multivector: comb[i] = sum_k w_k * score_k * templ[k][i]
    if (lane < 16) {
        float s = 0.f;
        for (int k = 0; k < 8; k++) {
            float t = templates[k * 16 + lane] + rmod[b][k * 16 + lane];
            s += wts[b][k] * sc[b][k] * t;
        }
        g_comb[b * 16 + lane] = s;
    }
}

// ---------------------------------------------------------------------------
// Kernel C: y = comb * x (geometric product), signs baked at compile time.
// Each thread handles 2 cells (front-batched 8x LDG.128); no shared memory.
// ---------------------------------------------------------------------------
__global__ void gss_apply_kernel(const float* __restrict__ state,
                                 float* __restrict__ out) {
    int b = blockIdx.y;

    // comb in registers (uniform per batch; L1-broadcast)
    const float4* cp = (const float4*)(g_comb + b * 16);
    float4 a0 = cp[0], a1 = cp[1], a2 = cp[2], a3 = cp[3];
    float a[16] = {a0.x, a0.y, a0.z, a0.w, a1.x, a1.y, a1.z, a1.w,
                   a2.x, a2.y, a2.z, a2.w, a3.x, a3.y, a3.z, a3.w};

    const size_t base4 = (size_t)b * N_ * 4;  // float4 units
    const float4* src = (const float4*)state + base4;
    float4* dst = (float4*)out + base4;

    const int TPB = NBLK * C_THREADS;          // 32768 threads per batch
    int n0 = blockIdx.x * C_THREADS + threadIdx.x;
    int n1 = n0 + TPB;                         // second cell, far-strided

    // front-batched loads: 8 independent LDG.128
    float4 p0 = src[n0 * 4 + 0];
    float4 p1 = src[n0 * 4 + 1];
    float4 p2 = src[n0 * 4 + 2];
    float4 p3 = src[n0 * 4 + 3];
    float4 q0 = src[n1 * 4 + 0];
    float4 q1 = src[n1 * 4 + 1];
    float4 q2 = src[n1 * 4 + 2];
    float4 q3 = src[n1 * 4 + 3];

    float x0[16] = {p0.x, p0.y, p0.z, p0.w, p1.x, p1.y, p1.z, p1.w,
                    p2.x, p2.y, p2.z, p2.w, p3.x, p3.y, p3.z, p3.w};
    float x1[16] = {q0.x, q0.y, q0.z, q0.w, q1.x, q1.y, q1.z, q1.w,
                    q2.x, q2.y, q2.z, q2.w, q3.x, q3.y, q3.z, q3.w};

    float y0[16], y1[16];
#pragma unroll
    for (int l = 0; l < 16; l++) {
        float s0 = 0.f, s1 = 0.f;
#pragma unroll
        for (int j = 0; j < 16; j++) {
            const float sgn = csign(j ^ l, j);   // compile-time constant
            if (sgn > 0.5f) {
                s0 = fmaf(a[j ^ l], x0[j], s0);
                s1 = fmaf(a[j ^ l], x1[j], s1);
            } else if (sgn < -0.5f) {
                s0 = fmaf(-a[j ^ l], x0[j], s0);
                s1 = fmaf(-a[j ^ l], x1[j], s1);
            }
        }
        y0[l] = s0; y1[l] = s1;
    }

    dst[n0 * 4 + 0] = make_float4(y0[0],  y0[1],  y0[2],  y0[3]);
    dst[n0 * 4 + 1] = make_float4(y0[4],  y0[5],  y0[6],  y0[7]);
    dst[n0 * 4 + 2] = make_float4(y0[8],  y0[9],  y0[10], y0[11]);
    dst[n0 * 4 + 3] = make_float4(y0[12], y0[13], y0[14], y0[15]);
    dst[n1 * 4 + 0] = make_float4(y1[0],  y1[1],  y1[2],  y1[3]);
    dst[n1 * 4 + 1] = make_float4(y1[4],  y1[5],  y1[6],  y1[7]);
    dst[n1 * 4 + 2] = make_float4(y1[8],  y1[9],  y1[10], y1[11]);
    dst[n1 * 4 + 3] = make_float4(y1[12], y1[13], y1[14], y1[15]);
}

extern "C" void kernel_launch(void* const* d_in, const int* in_sizes, int n_in,
                              void* d_out, int out_size) {
    const float* cpu_state   = (const float*)d_in[0];
    const float* ctrl_cursor = (const float*)d_in[1];
    const float* rule_memory = (const float*)d_in[2];
    const float* templates   = (const float*)d_in[3];
    const float* W1          = (const float*)d_in[4];
    const float* b1          = (const float*)d_in[5];
    const float* W2          = (const float*)d_in[6];
    const float* b2          = (const float*)d_in[7];
    const float* Wr          = (const float*)d_in[8];
    const float* br          = (const float*)d_in[9];
    const float* log_temp    = (const float*)d_in[10];
    float* out = (float*)d_out;

    dim3 gA(NBLK, B_);
    gss_reduce_kernel<<<gA, RED_THREADS>>>(cpu_state);

    gss_small_kernel<<<1, 256>>>(ctrl_cursor, rule_memory, templates,
                                 W1, b1, W2, b2, Wr, br, log_temp);

    dim3 gC(NBLK, B_);
    gss_apply_kernel<<<gC, C_THREADS>>>(cpu_state, out);
}